// round 1
// baseline (speedup 1.0000x reference)
#include <cuda_runtime.h>
#include <math.h>

// ---------------- problem constants ----------------
#define BB   8
#define TT   2048
#define CC   1024
#define EE   8
#define KTOP 2
#define CAPQ 320
#define HH   4096                  // 4*C
#define BT   (BB*TT)               // 16384 tokens
#define NSLOT (EE*BB*CAPQ)         // 20480 expert slots
#define ROWS_E (BB*CAPQ)           // 2560 rows per expert

// ---------------- scratch (static device globals; no allocation) ----------------
__device__ float g_h1[(size_t)BT * HH];            // 268 MB
__device__ float g_h2[(size_t)BT * HH];            // 268 MB
__device__ float g_eh[(size_t)EE * ROWS_E * HH];   // 335 MB
__device__ float g_ey[(size_t)EE * ROWS_E * CC];   //  84 MB
__device__ float g_topk_p[BT * KTOP];
__device__ int   g_topk_e[BT * KTOP];
__device__ int   g_dest[BT * KTOP];
__device__ int   g_slot_tok[NSLOT];

// ---------------- generic fp32 GEMM:  C[z] = act(A[z] @ W[z] + b[z]) ----------------
// A row-major [M,K] (optionally gathered rows from a token table), W row-major [K,N].
// Tile 128x128x8, 256 threads, 8x8 accum per thread. M%128==0, N%128==0, K%8==0 hold
// for every call in this problem, so no bounds checks.
__global__ __launch_bounds__(256)
void sgemm_kernel(const float* __restrict__ A, long long Astride,
                  const float* __restrict__ W, long long Wstride,
                  const float* __restrict__ bias, long long bstride,
                  float* __restrict__ Cmat, long long Cstride,
                  const int* __restrict__ gidx, int gstride,
                  int M, int N, int K, int relu)
{
    const int z = blockIdx.z;
    const float* Wb = W + (long long)z * Wstride;
    const float* bb = bias + (long long)z * bstride;
    float* Cb = Cmat + (long long)z * Cstride;

    __shared__ float As[8][128];
    __shared__ float Bs[8][128];

    const int tid = threadIdx.x;
    const int m0 = blockIdx.y * 128;
    const int n0 = blockIdx.x * 128;

    // A tile loader: 128 rows x 8 cols, one float4 per thread
    const int arow = tid >> 1;
    const int acol = (tid & 1) << 2;
    // B tile loader: 8 rows x 128 cols, one float4 per thread
    const int brow = tid >> 5;
    const int bcol = (tid & 31) << 2;

    const float* aptr;
    bool avalid = true;
    if (gidx) {
        int tok = gidx[(long long)z * gstride + m0 + arow];
        if (tok >= 0) aptr = A + (long long)tok * K + acol;
        else { avalid = false; aptr = A; }   // padded slot -> zeros
    } else {
        aptr = A + (long long)z * Astride + (long long)(m0 + arow) * K + acol;
    }
    const float* bptr = Wb + (long long)brow * N + n0 + bcol;

    const int tx = tid & 15;
    const int ty = tid >> 4;
    float acc[8][8];
#pragma unroll
    for (int i = 0; i < 8; i++)
#pragma unroll
        for (int j = 0; j < 8; j++) acc[i][j] = 0.f;

    for (int k0 = 0; k0 < K; k0 += 8) {
        float4 av = avalid ? *(const float4*)aptr : make_float4(0.f, 0.f, 0.f, 0.f);
        float4 bv = *(const float4*)bptr;
        __syncthreads();
        As[acol + 0][arow] = av.x;
        As[acol + 1][arow] = av.y;
        As[acol + 2][arow] = av.z;
        As[acol + 3][arow] = av.w;
        *(float4*)&Bs[brow][bcol] = bv;
        __syncthreads();
#pragma unroll
        for (int kk = 0; kk < 8; kk++) {
            float4 a0 = *(const float4*)&As[kk][ty * 8];
            float4 a1 = *(const float4*)&As[kk][ty * 8 + 4];
            float4 b0 = *(const float4*)&Bs[kk][tx * 8];
            float4 b1 = *(const float4*)&Bs[kk][tx * 8 + 4];
            float a[8] = {a0.x, a0.y, a0.z, a0.w, a1.x, a1.y, a1.z, a1.w};
            float b[8] = {b0.x, b0.y, b0.z, b0.w, b1.x, b1.y, b1.z, b1.w};
#pragma unroll
            for (int i = 0; i < 8; i++)
#pragma unroll
                for (int j = 0; j < 8; j++)
                    acc[i][j] += a[i] * b[j];
        }
        if (avalid) aptr += 8;
        bptr += (long long)8 * N;
    }

#pragma unroll
    for (int i = 0; i < 8; i++) {
        int row = m0 + ty * 8 + i;
        float* crow = Cb + (long long)row * N + n0 + tx * 8;
#pragma unroll
        for (int j0 = 0; j0 < 8; j0 += 4) {
            float4 o;
            o.x = acc[i][j0 + 0] + bb[n0 + tx * 8 + j0 + 0];
            o.y = acc[i][j0 + 1] + bb[n0 + tx * 8 + j0 + 1];
            o.z = acc[i][j0 + 2] + bb[n0 + tx * 8 + j0 + 2];
            o.w = acc[i][j0 + 3] + bb[n0 + tx * 8 + j0 + 3];
            if (relu) {
                o.x = fmaxf(o.x, 0.f); o.y = fmaxf(o.y, 0.f);
                o.z = fmaxf(o.z, 0.f); o.w = fmaxf(o.w, 0.f);
            }
            *(float4*)(crow + j0) = o;
        }
    }
}

// ---------------- router: logits = h2 @ Wr3 + br3, softmax, top-2 ----------------
// one warp per token
__global__ __launch_bounds__(128)
void router_topk_kernel(const float* __restrict__ h2, const float* __restrict__ Wr3,
                        const float* __restrict__ br3,
                        float* __restrict__ topk_p, int* __restrict__ topk_e)
{
    int warp = (blockIdx.x * blockDim.x + threadIdx.x) >> 5;
    int lane = threadIdx.x & 31;
    if (warp >= BT) return;
    const float* row = h2 + (long long)warp * HH;

    float acc[EE];
#pragma unroll
    for (int e = 0; e < EE; e++) acc[e] = 0.f;

    for (int k = lane * 4; k < HH; k += 128) {
        float4 v = *(const float4*)(row + k);
        float vv[4] = {v.x, v.y, v.z, v.w};
#pragma unroll
        for (int j = 0; j < 4; j++) {
            const float* w = Wr3 + (long long)(k + j) * EE;
            float xv = vv[j];
#pragma unroll
            for (int e = 0; e < EE; e++) acc[e] += xv * w[e];
        }
    }
#pragma unroll
    for (int e = 0; e < EE; e++)
#pragma unroll
        for (int off = 16; off > 0; off >>= 1)
            acc[e] += __shfl_xor_sync(0xFFFFFFFFu, acc[e], off);

    if (lane == 0) {
        float lg[EE];
        float mx = -1e30f;
#pragma unroll
        for (int e = 0; e < EE; e++) { lg[e] = acc[e] + br3[e]; mx = fmaxf(mx, lg[e]); }
        float p[EE]; float s = 0.f;
#pragma unroll
        for (int e = 0; e < EE; e++) { p[e] = __expf(lg[e] - mx); s += p[e]; }
        float inv = 1.f / s;
        // top-2 on logits (same order as probs); strict '>' keeps lowest index on tie,
        // matching jax.lax.top_k
        int i0 = 0;
#pragma unroll
        for (int e = 1; e < EE; e++) if (lg[e] > lg[i0]) i0 = e;
        int i1 = (i0 == 0) ? 1 : 0;
#pragma unroll
        for (int e = 0; e < EE; e++) if (e != i0 && lg[e] > lg[i1]) i1 = e;
        topk_p[warp * 2 + 0] = p[i0] * inv;
        topk_p[warp * 2 + 1] = p[i1] * inv;
        topk_e[warp * 2 + 0] = i0;
        topk_e[warp * 2 + 1] = i1;
    }
}

// ---------------- slot table init ----------------
__global__ void init_slots_kernel(int* slot_tok)
{
    int i = blockIdx.x * 256 + threadIdx.x;
    if (i < NSLOT) slot_tok[i] = -1;
}

// ---------------- deterministic capacity scan (row-major over (t,k) per batch row) ----
__global__ void route_scan_kernel(const int* __restrict__ topk_e,
                                  int* __restrict__ dest, int* __restrict__ slot_tok)
{
    int b = blockIdx.x;
    int e = threadIdx.x;
    if (e >= EE) return;
    int cnt = 0;
    for (int t = 0; t < TT; t++) {
#pragma unroll
        for (int k = 0; k < KTOP; k++) {
            int idx = (b * TT + t) * KTOP + k;
            if (topk_e[idx] == e) {
                if (cnt < CAPQ) {
                    int s = e * (BB * CAPQ) + b * CAPQ + cnt;
                    dest[idx] = s;
                    slot_tok[s] = b * TT + t;
                } else {
                    dest[idx] = -1;   // dropped
                }
                cnt++;
            }
        }
    }
}

// ---------------- combine: out[tok] = sum_k p_k * ey[slot_k] ----------------
__global__ __launch_bounds__(256)
void combine_kernel(const float* __restrict__ ey, const float* __restrict__ topk_p,
                    const int* __restrict__ dest, float* __restrict__ out)
{
    int tok = blockIdx.x;
    int c = threadIdx.x * 4;
    float4 r = make_float4(0.f, 0.f, 0.f, 0.f);
#pragma unroll
    for (int k = 0; k < KTOP; k++) {
        int s = dest[tok * 2 + k];
        if (s >= 0) {
            float p = topk_p[tok * 2 + k];
            float4 v = *(const float4*)(ey + (long long)s * CC + c);
            r.x += p * v.x; r.y += p * v.y; r.z += p * v.z; r.w += p * v.w;
        }
    }
    *(float4*)(out + (long long)tok * CC + c) = r;
}

// ---------------- launch ----------------
extern "C" void kernel_launch(void* const* d_in, const int* in_sizes, int n_in,
                              void* d_out, int out_size)
{
    (void)in_sizes; (void)n_in; (void)out_size;
    const float* x   = (const float*)d_in[0];
    const float* Wr1 = (const float*)d_in[1];
    const float* br1 = (const float*)d_in[2];
    const float* Wr2 = (const float*)d_in[3];
    const float* br2 = (const float*)d_in[4];
    const float* Wr3 = (const float*)d_in[5];
    const float* br3 = (const float*)d_in[6];
    const float* We1 = (const float*)d_in[7];
    const float* be1 = (const float*)d_in[8];
    const float* We2 = (const float*)d_in[9];
    const float* be2 = (const float*)d_in[10];
    float* out = (float*)d_out;

    float *h1, *h2, *eh, *ey, *tp;
    int *te, *dest, *stok;
    cudaGetSymbolAddress((void**)&h1,   g_h1);
    cudaGetSymbolAddress((void**)&h2,   g_h2);
    cudaGetSymbolAddress((void**)&eh,   g_eh);
    cudaGetSymbolAddress((void**)&ey,   g_ey);
    cudaGetSymbolAddress((void**)&tp,   g_topk_p);
    cudaGetSymbolAddress((void**)&te,   g_topk_e);
    cudaGetSymbolAddress((void**)&dest, g_dest);
    cudaGetSymbolAddress((void**)&stok, g_slot_tok);

    // 1) h1 = relu(x @ Wr1 + br1)      [16384,1024]x[1024,4096]
    sgemm_kernel<<<dim3(HH / 128, BT / 128, 1), 256>>>(
        x, 0, Wr1, 0, br1, 0, h1, 0, nullptr, 0, BT, HH, CC, 1);

    // 2) h2 = relu(h1 @ Wr2 + br2)     [16384,4096]x[4096,4096]
    sgemm_kernel<<<dim3(HH / 128, BT / 128, 1), 256>>>(
        h1, 0, Wr2, 0, br2, 0, h2, 0, nullptr, 0, BT, HH, HH, 1);

    // 3) logits -> softmax -> top-2
    router_topk_kernel<<<(BT * 32) / 128, 128>>>(h2, Wr3, br3, tp, te);

    // 4) routing tables
    init_slots_kernel<<<(NSLOT + 255) / 256, 256>>>(stok);
    route_scan_kernel<<<BB, 32>>>(te, dest, stok);

    // 5) expert FFN layer 1 (gathered A):  eh[e] = relu(gather(x) @ We1[e] + be1[e])
    sgemm_kernel<<<dim3(HH / 128, ROWS_E / 128, EE), 256>>>(
        x, 0,
        We1, (long long)CC * HH,
        be1, HH,
        eh, (long long)ROWS_E * HH,
        stok, ROWS_E,
        ROWS_E, HH, CC, 1);

    // 6) expert FFN layer 2:  ey[e] = eh[e] @ We2[e] + be2[e]
    sgemm_kernel<<<dim3(CC / 128, ROWS_E / 128, EE), 256>>>(
        eh, (long long)ROWS_E * HH,
        We2, (long long)HH * CC,
        be2, CC,
        ey, (long long)ROWS_E * CC,
        nullptr, 0,
        ROWS_E, CC, HH, 0);

    // 7) combine
    combine_kernel<<<BT, 256>>>(ey, tp, dest, out);
}

// round 2
// speedup vs baseline: 1.6085x; 1.6085x over previous
#include <cuda_runtime.h>
#include <math.h>

// ---------------- problem constants ----------------
#define BB   8
#define TT   2048
#define CC   1024
#define EE   8
#define KTOP 2
#define CAPQ 320
#define HH   4096                  // 4*C
#define BT   (BB*TT)               // 16384 tokens
#define NSLOT (EE*BB*CAPQ)         // 20480 expert slots
#define ROWS_E (BB*CAPQ)           // 2560 rows per expert

// ---------------- scratch (static device globals; no allocation) ----------------
__device__ float g_h1[(size_t)BT * HH];            // 268 MB
__device__ float g_h2[(size_t)BT * HH];            // 268 MB
__device__ float g_eh[(size_t)EE * ROWS_E * HH];   // 335 MB
__device__ float g_ey[(size_t)EE * ROWS_E * CC];   //  84 MB
__device__ float g_topk_p[BT * KTOP];
__device__ int   g_topk_e[BT * KTOP];
__device__ int   g_dest[BT * KTOP];
__device__ int   g_slot_tok[NSLOT];

// ---------------- generic fp32 GEMM:  C[z] = act(A[z] @ W[z] + b[z]) ----------------
// A row-major [M,K] (optionally gathered rows from a token table), W row-major [K,N].
// Tile 128x128x8, 256 threads, 8x8 accum per thread. M%128==0, N%128==0, K%8==0 hold
// for every call in this problem, so no bounds checks.
__global__ __launch_bounds__(256)
void sgemm_kernel(const float* __restrict__ A, long long Astride,
                  const float* __restrict__ W, long long Wstride,
                  const float* __restrict__ bias, long long bstride,
                  float* __restrict__ Cmat, long long Cstride,
                  const int* __restrict__ gidx, int gstride,
                  int M, int N, int K, int relu)
{
    const int z = blockIdx.z;
    const float* Wb = W + (long long)z * Wstride;
    const float* bb = bias + (long long)z * bstride;
    float* Cb = Cmat + (long long)z * Cstride;

    __shared__ float As[8][128];
    __shared__ float Bs[8][128];

    const int tid = threadIdx.x;
    const int m0 = blockIdx.y * 128;
    const int n0 = blockIdx.x * 128;

    // A tile loader: 128 rows x 8 cols, one float4 per thread
    const int arow = tid >> 1;
    const int acol = (tid & 1) << 2;
    // B tile loader: 8 rows x 128 cols, one float4 per thread
    const int brow = tid >> 5;
    const int bcol = (tid & 31) << 2;

    const float* aptr;
    bool avalid = true;
    if (gidx) {
        int tok = gidx[(long long)z * gstride + m0 + arow];
        if (tok >= 0) aptr = A + (long long)tok * K + acol;
        else { avalid = false; aptr = A; }   // padded slot -> zeros
    } else {
        aptr = A + (long long)z * Astride + (long long)(m0 + arow) * K + acol;
    }
    const float* bptr = Wb + (long long)brow * N + n0 + bcol;

    const int tx = tid & 15;
    const int ty = tid >> 4;
    float acc[8][8];
#pragma unroll
    for (int i = 0; i < 8; i++)
#pragma unroll
        for (int j = 0; j < 8; j++) acc[i][j] = 0.f;

    for (int k0 = 0; k0 < K; k0 += 8) {
        float4 av = avalid ? *(const float4*)aptr : make_float4(0.f, 0.f, 0.f, 0.f);
        float4 bv = *(const float4*)bptr;
        __syncthreads();
        As[acol + 0][arow] = av.x;
        As[acol + 1][arow] = av.y;
        As[acol + 2][arow] = av.z;
        As[acol + 3][arow] = av.w;
        *(float4*)&Bs[brow][bcol] = bv;
        __syncthreads();
#pragma unroll
        for (int kk = 0; kk < 8; kk++) {
            float4 a0 = *(const float4*)&As[kk][ty * 8];
            float4 a1 = *(const float4*)&As[kk][ty * 8 + 4];
            float4 b0 = *(const float4*)&Bs[kk][tx * 8];
            float4 b1 = *(const float4*)&Bs[kk][tx * 8 + 4];
            float a[8] = {a0.x, a0.y, a0.z, a0.w, a1.x, a1.y, a1.z, a1.w};
            float b[8] = {b0.x, b0.y, b0.z, b0.w, b1.x, b1.y, b1.z, b1.w};
#pragma unroll
            for (int i = 0; i < 8; i++)
#pragma unroll
                for (int j = 0; j < 8; j++)
                    acc[i][j] += a[i] * b[j];
        }
        if (avalid) aptr += 8;
        bptr += (long long)8 * N;
    }

#pragma unroll
    for (int i = 0; i < 8; i++) {
        int row = m0 + ty * 8 + i;
        float* crow = Cb + (long long)row * N + n0 + tx * 8;
#pragma unroll
        for (int j0 = 0; j0 < 8; j0 += 4) {
            float4 o;
            o.x = acc[i][j0 + 0] + bb[n0 + tx * 8 + j0 + 0];
            o.y = acc[i][j0 + 1] + bb[n0 + tx * 8 + j0 + 1];
            o.z = acc[i][j0 + 2] + bb[n0 + tx * 8 + j0 + 2];
            o.w = acc[i][j0 + 3] + bb[n0 + tx * 8 + j0 + 3];
            if (relu) {
                o.x = fmaxf(o.x, 0.f); o.y = fmaxf(o.y, 0.f);
                o.z = fmaxf(o.z, 0.f); o.w = fmaxf(o.w, 0.f);
            }
            *(float4*)(crow + j0) = o;
        }
    }
}

// ---------------- router: logits = h2 @ Wr3 + br3, softmax, top-2 ----------------
// one warp per token
__global__ __launch_bounds__(128)
void router_topk_kernel(const float* __restrict__ h2, const float* __restrict__ Wr3,
                        const float* __restrict__ br3,
                        float* __restrict__ topk_p, int* __restrict__ topk_e)
{
    int warp = (blockIdx.x * blockDim.x + threadIdx.x) >> 5;
    int lane = threadIdx.x & 31;
    if (warp >= BT) return;
    const float* row = h2 + (long long)warp * HH;

    float acc[EE];
#pragma unroll
    for (int e = 0; e < EE; e++) acc[e] = 0.f;

    for (int k = lane * 4; k < HH; k += 128) {
        float4 v = *(const float4*)(row + k);
        float vv[4] = {v.x, v.y, v.z, v.w};
#pragma unroll
        for (int j = 0; j < 4; j++) {
            const float* w = Wr3 + (long long)(k + j) * EE;
            float xv = vv[j];
#pragma unroll
            for (int e = 0; e < EE; e++) acc[e] += xv * w[e];
        }
    }
#pragma unroll
    for (int e = 0; e < EE; e++)
#pragma unroll
        for (int off = 16; off > 0; off >>= 1)
            acc[e] += __shfl_xor_sync(0xFFFFFFFFu, acc[e], off);

    if (lane == 0) {
        float lg[EE];
        float mx = -1e30f;
#pragma unroll
        for (int e = 0; e < EE; e++) { lg[e] = acc[e] + br3[e]; mx = fmaxf(mx, lg[e]); }
        float p[EE]; float s = 0.f;
#pragma unroll
        for (int e = 0; e < EE; e++) { p[e] = __expf(lg[e] - mx); s += p[e]; }
        float inv = 1.f / s;
        // top-2 on logits (same order as probs); strict '>' keeps lowest index on tie,
        // matching jax.lax.top_k
        int i0 = 0;
#pragma unroll
        for (int e = 1; e < EE; e++) if (lg[e] > lg[i0]) i0 = e;
        int i1 = (i0 == 0) ? 1 : 0;
#pragma unroll
        for (int e = 0; e < EE; e++) if (e != i0 && lg[e] > lg[i1]) i1 = e;
        topk_p[warp * 2 + 0] = p[i0] * inv;
        topk_p[warp * 2 + 1] = p[i1] * inv;
        topk_e[warp * 2 + 0] = i0;
        topk_e[warp * 2 + 1] = i1;
    }
}

// ---------------- slot table init ----------------
__global__ void init_slots_kernel(int* slot_tok)
{
    int i = blockIdx.x * 256 + threadIdx.x;
    if (i < NSLOT) slot_tok[i] = -1;
}

// ---------------- deterministic capacity scan (row-major over (t,k) per batch row) ----
__global__ void route_scan_kernel(const int* __restrict__ topk_e,
                                  int* __restrict__ dest, int* __restrict__ slot_tok)
{
    int b = blockIdx.x;
    int e = threadIdx.x;
    if (e >= EE) return;
    int cnt = 0;
    for (int t = 0; t < TT; t++) {
#pragma unroll
        for (int k = 0; k < KTOP; k++) {
            int idx = (b * TT + t) * KTOP + k;
            if (topk_e[idx] == e) {
                if (cnt < CAPQ) {
                    int s = e * (BB * CAPQ) + b * CAPQ + cnt;
                    dest[idx] = s;
                    slot_tok[s] = b * TT + t;
                } else {
                    dest[idx] = -1;   // dropped
                }
                cnt++;
            }
        }
    }
}

// ---------------- combine: out[tok] = sum_k p_k * ey[slot_k] ----------------
__global__ __launch_bounds__(256)
void combine_kernel(const float* __restrict__ ey, const float* __restrict__ topk_p,
                    const int* __restrict__ dest, float* __restrict__ out)
{
    int tok = blockIdx.x;
    int c = threadIdx.x * 4;
    float4 r = make_float4(0.f, 0.f, 0.f, 0.f);
#pragma unroll
    for (int k = 0; k < KTOP; k++) {
        int s = dest[tok * 2 + k];
        if (s >= 0) {
            float p = topk_p[tok * 2 + k];
            float4 v = *(const float4*)(ey + (long long)s * CC + c);
            r.x += p * v.x; r.y += p * v.y; r.z += p * v.z; r.w += p * v.w;
        }
    }
    *(float4*)(out + (long long)tok * CC + c) = r;
}

// ---------------- launch ----------------
extern "C" void kernel_launch(void* const* d_in, const int* in_sizes, int n_in,
                              void* d_out, int out_size)
{
    (void)in_sizes; (void)n_in; (void)out_size;
    const float* x   = (const float*)d_in[0];
    const float* Wr1 = (const float*)d_in[1];
    const float* br1 = (const float*)d_in[2];
    const float* Wr2 = (const float*)d_in[3];
    const float* br2 = (const float*)d_in[4];
    const float* Wr3 = (const float*)d_in[5];
    const float* br3 = (const float*)d_in[6];
    const float* We1 = (const float*)d_in[7];
    const float* be1 = (const float*)d_in[8];
    const float* We2 = (const float*)d_in[9];
    const float* be2 = (const float*)d_in[10];
    float* out = (float*)d_out;

    float *h1, *h2, *eh, *ey, *tp;
    int *te, *dest, *stok;
    cudaGetSymbolAddress((void**)&h1,   g_h1);
    cudaGetSymbolAddress((void**)&h2,   g_h2);
    cudaGetSymbolAddress((void**)&eh,   g_eh);
    cudaGetSymbolAddress((void**)&ey,   g_ey);
    cudaGetSymbolAddress((void**)&tp,   g_topk_p);
    cudaGetSymbolAddress((void**)&te,   g_topk_e);
    cudaGetSymbolAddress((void**)&dest, g_dest);
    cudaGetSymbolAddress((void**)&stok, g_slot_tok);

    // 1) h1 = relu(x @ Wr1 + br1)      [16384,1024]x[1024,4096]
    sgemm_kernel<<<dim3(HH / 128, BT / 128, 1), 256>>>(
        x, 0, Wr1, 0, br1, 0, h1, 0, nullptr, 0, BT, HH, CC, 1);

    // 2) h2 = relu(h1 @ Wr2 + br2)     [16384,4096]x[4096,4096]
    sgemm_kernel<<<dim3(HH / 128, BT / 128, 1), 256>>>(
        h1, 0, Wr2, 0, br2, 0, h2, 0, nullptr, 0, BT, HH, HH, 1);

    // 3) logits -> softmax -> top-2
    router_topk_kernel<<<(BT * 32) / 128, 128>>>(h2, Wr3, br3, tp, te);

    // 4) routing tables
    init_slots_kernel<<<(NSLOT + 255) / 256, 256>>>(stok);
    route_scan_kernel<<<BB, 32>>>(te, dest, stok);

    // 5) expert FFN layer 1 (gathered A):  eh[e] = relu(gather(x) @ We1[e] + be1[e])
    sgemm_kernel<<<dim3(HH / 128, ROWS_E / 128, EE), 256>>>(
        x, 0,
        We1, (long long)CC * HH,
        be1, HH,
        eh, (long long)ROWS_E * HH,
        stok, ROWS_E,
        ROWS_E, HH, CC, 1);

    // 6) expert FFN layer 2:  ey[e] = eh[e] @ We2[e] + be2[e]
    sgemm_kernel<<<dim3(CC / 128, ROWS_E / 128, EE), 256>>>(
        eh, (long long)ROWS_E * HH,
        We2, (long long)HH * CC,
        be2, CC,
        ey, (long long)ROWS_E * CC,
        nullptr, 0,
        ROWS_E, CC, HH, 0);

    // 7) combine
    combine_kernel<<<BT, 256>>>(ey, tp, dest, out);
}

// round 4
// speedup vs baseline: 2.4839x; 1.5442x over previous
#include <cuda_runtime.h>
#include <cuda_bf16.h>
#include <stdint.h>

#define BB   8
#define TT   2048
#define CC   1024
#define EE   8
#define KTOP 2
#define CAPQ 320
#define HH   4096
#define BT   (BB*TT)
#define NSLOT (EE*BB*CAPQ)
#define ROWS_E (BB*CAPQ)

typedef __nv_bfloat16 bf16;
typedef long long ll;

// ---------------- scratch ----------------
__device__ bf16  g_xs  [3ll*BT*CC];
__device__ bf16  g_wr1t[3ll*HH*CC];
__device__ bf16  g_wr2t[3ll*HH*HH];
__device__ bf16  g_we1t[2ll*EE*HH*CC];
__device__ bf16  g_we2t[2ll*EE*CC*HH];
__device__ bf16  g_h1s [3ll*BT*HH];
__device__ bf16  g_h2s [3ll*BT*HH];
__device__ bf16  g_ehs [2ll*EE*ROWS_E*HH];
__device__ float g_ey  [(ll)EE*ROWS_E*CC];
__device__ float g_topk_p[BT*KTOP];
__device__ int   g_topk_e[BT*KTOP];
__device__ int   g_dest[BT*KTOP];
__device__ int   g_slot_tok[NSLOT];

// ---------------- PTX helpers (base-target only: cp.async / ldmatrix / mma.sync) ----
__device__ __forceinline__ uint32_t smem_u32(const void* p) {
    uint32_t a;
    asm("{ .reg .u64 t; cvta.to.shared.u64 t, %1; cvt.u32.u64 %0, t; }" : "=r"(a) : "l"(p));
    return a;
}
__device__ __forceinline__ void cp16(uint32_t dst, const void* src, int ssz) {
    asm volatile("cp.async.cg.shared.global [%0], [%1], 16, %2;" :: "r"(dst), "l"(src), "r"(ssz));
}
__device__ __forceinline__ void cp_commit() { asm volatile("cp.async.commit_group;" ::: "memory"); }
template<int N> __device__ __forceinline__ void cp_wait() {
    asm volatile("cp.async.wait_group %0;" :: "n"(N) : "memory");
}
__device__ __forceinline__ void ldsm4(uint32_t* r, uint32_t addr) {
    asm volatile("ldmatrix.sync.aligned.m8n8.x4.shared.b16 {%0,%1,%2,%3}, [%4];"
        : "=r"(r[0]), "=r"(r[1]), "=r"(r[2]), "=r"(r[3]) : "r"(addr));
}
__device__ __forceinline__ void mma_bf16(float* c, const uint32_t* a, const uint32_t* b) {
    asm volatile("mma.sync.aligned.m16n8k16.row.col.f32.bf16.bf16.f32 "
        "{%0,%1,%2,%3}, {%4,%5,%6,%7}, {%8,%9}, {%0,%1,%2,%3};"
        : "+f"(c[0]), "+f"(c[1]), "+f"(c[2]), "+f"(c[3])
        : "r"(a[0]), "r"(a[1]), "r"(a[2]), "r"(a[3]), "r"(b[0]), "r"(b[1]));
}

// ---------------- splitting helpers ----------------
__device__ __forceinline__ void split3v(float v, uint16_t* h, uint16_t* m, uint16_t* l) {
    bf16 hb = __float2bfloat16(v);
    float r1 = v - __bfloat162float(hb);
    bf16 mb = __float2bfloat16(r1);
    bf16 lb = __float2bfloat16(r1 - __bfloat162float(mb));
    *h = *(uint16_t*)&hb; *m = *(uint16_t*)&mb; *l = *(uint16_t*)&lb;
}

__global__ __launch_bounds__(256)
void split3_kernel(const float* __restrict__ in, bf16* __restrict__ out, ll ps) {
    ll i = ((ll)blockIdx.x * 256 + threadIdx.x) * 4;
    float4 v = *(const float4*)(in + i);
    uint16_t h[4], m[4], l[4];
    split3v(v.x, h+0, m+0, l+0); split3v(v.y, h+1, m+1, l+1);
    split3v(v.z, h+2, m+2, l+2); split3v(v.w, h+3, m+3, l+3);
    *(uint2*)(out + i)        = *(uint2*)h;
    *(uint2*)(out + ps + i)   = *(uint2*)m;
    *(uint2*)(out + 2*ps + i) = *(uint2*)l;
}

// W[z][K][N] -> planes [p][z][N][K]
__global__ void transpose_split_kernel(const float* __restrict__ W, bf16* __restrict__ out,
                                       int K, int N, ll ps, int nplanes) {
    __shared__ float t[32][33];
    int z = blockIdx.z;
    const float* Wz = W + (ll)z * K * N;
    int n0 = blockIdx.x * 32, k0 = blockIdx.y * 32;
    for (int dy = threadIdx.y; dy < 32; dy += 8)
        t[dy][threadIdx.x] = Wz[(ll)(k0 + dy) * N + n0 + threadIdx.x];
    __syncthreads();
    for (int dy = threadIdx.y; dy < 32; dy += 8) {
        float v = t[threadIdx.x][dy];
        uint16_t h, m, l;
        split3v(v, &h, &m, &l);
        ll o = (ll)z * N * K + (ll)(n0 + dy) * K + k0 + threadIdx.x;
        *(uint16_t*)(out + o) = h;
        *(uint16_t*)(out + ps + o) = m;
        if (nplanes == 3) *(uint16_t*)(out + 2 * ps + o) = l;
    }
}

// ---------------- split-bf16 GEMM via mma.sync (HMMA) ----------------
// C[z] = act( sum_{ia+ib<NP} A_plane[ia] @ B_plane[ib]^T + bias ), A [M,K] (opt. gathered),
// B planes [z*N + n][K]. Tile 128x128x32, 8 warps (4m x 2n), padded SMEM rows (K32+8).
// OUTMODE: 0 = fp32 out; 1 = relu+split3 planes; 2 = relu+split2 planes.
template<int NP, int OUTMODE>
__global__ __launch_bounds__(256, 1)
void tc_gemm(const bf16* __restrict__ A, ll ApS, int ArowsPerZ,
             const bf16* __restrict__ B, ll BpS,
             const float* __restrict__ bias, int biasPerZ,
             void* __restrict__ outp, ll OpS, int MrowsPerZ,
             const int* __restrict__ gidx, int gstride,
             int N, int K, int gm, int gn)
{
    extern __shared__ char sm[];
    __shared__ int rowtok[128];
    const uint32_t smb = smem_u32(sm);
    const int tid = threadIdx.x;
    const int wid = tid >> 5, lane = tid & 31;
    const int z = blockIdx.y;

    // grouped rasterization for L2 reuse
    int bid = blockIdx.x;
    int grp = bid / (gn * 8);
    int rem = bid - grp * gn * 8;
    int gsz = gm - grp * 8; if (gsz > 8) gsz = 8;
    int mtile = grp * 8 + rem % gsz;
    int ntile = rem / gsz;
    const int m0 = mtile << 7, n0 = ntile << 7;

    if (tid < 128)
        rowtok[tid] = gidx ? gidx[(ll)z * gstride + m0 + tid] : (z * ArowsPerZ + m0 + tid);
    __syncthreads();

    const int PT = 10240;              // one plane tile: 128 rows x 80B
    const int stageB = NP * 2 * PT;
    const int nch = K >> 5;

    auto load_stage = [&](int s, int kc) {
        const int k0 = kc << 5;
        uint32_t sbase = smb + s * stageB;
#pragma unroll
        for (int u = tid; u < NP * 1024; u += 256) {
            int isB = u >= NP * 512;
            int uu = isB ? u - NP * 512 : u;
            int p = uu >> 9;
            int t = uu & 511;
            int r = t >> 2, c = t & 3;
            uint32_t dst = sbase + (uint32_t)((isB ? NP + p : p) * PT + r * 80 + c * 16);
            const bf16* src; int ssz = 16;
            if (!isB) {
                int ra = rowtok[r];
                if (ra < 0) { src = A; ssz = 0; }
                else src = A + (ll)p * ApS + (ll)ra * K + k0 + c * 8;
            } else {
                src = B + (ll)p * BpS + ((ll)z * N + n0 + r) * K + k0 + c * 8;
            }
            cp16(dst, src, ssz);
        }
    };

    const int wm = wid & 3, wn = wid >> 2;
    // per-lane ldmatrix offsets (bytes) within a plane tile
    const uint32_t a_off = (uint32_t)((wm * 32 + (lane & 7) + ((lane >> 3) & 1) * 8) * 80
                                      + (lane >> 4) * 16);
    const uint32_t b_off = (uint32_t)((wn * 64 + ((lane >> 4) & 1) * 8 + (lane & 7)) * 80
                                      + ((lane >> 3) & 1) * 16);

    float acc[2][8][4];
#pragma unroll
    for (int mt = 0; mt < 2; mt++)
#pragma unroll
        for (int nt = 0; nt < 8; nt++)
#pragma unroll
            for (int j = 0; j < 4; j++) acc[mt][nt][j] = 0.f;

    load_stage(0, 0); cp_commit();

    for (int i = 0; i < nch; i++) {
        int cur = i & 1;
        if (i + 1 < nch) { load_stage(cur ^ 1, i + 1); cp_commit(); cp_wait<1>(); }
        else             { cp_wait<0>(); }
        __syncthreads();
        uint32_t sbase = smb + cur * stageB;
#pragma unroll
        for (int ks = 0; ks < 2; ks++) {
            uint32_t aF[NP][2][4];
#pragma unroll
            for (int p = 0; p < NP; p++)
#pragma unroll
                for (int mt = 0; mt < 2; mt++)
                    ldsm4(aF[p][mt], sbase + p * PT + mt * 16 * 80 + ks * 32 + a_off);
#pragma unroll
            for (int ib = 0; ib < NP; ib++) {
                uint32_t bF[8][2];
#pragma unroll
                for (int q = 0; q < 4; q++) {
                    uint32_t r4[4];
                    ldsm4(r4, sbase + (NP + ib) * PT + q * 1280 + ks * 32 + b_off);
                    bF[q*2][0] = r4[0]; bF[q*2][1] = r4[1];
                    bF[q*2+1][0] = r4[2]; bF[q*2+1][1] = r4[3];
                }
#pragma unroll
                for (int ia = 0; ia < NP; ia++) {
                    if (ia + ib >= NP) continue;
#pragma unroll
                    for (int mt = 0; mt < 2; mt++)
#pragma unroll
                        for (int nt = 0; nt < 8; nt++)
                            mma_bf16(acc[mt][nt], aF[ia][mt], bF[nt]);
                }
            }
        }
        __syncthreads();
    }

    // ---- epilogue: stage fp32 tile in SMEM, then coalesced bias/relu/split ----
    float* ep = (float*)sm;
#pragma unroll
    for (int mt = 0; mt < 2; mt++) {
        int r0 = wm * 32 + mt * 16 + (lane >> 2);
#pragma unroll
        for (int nt = 0; nt < 8; nt++) {
            int col = wn * 64 + nt * 8 + (lane & 3) * 2;
            ep[r0 * 132 + col]       = acc[mt][nt][0];
            ep[r0 * 132 + col + 1]   = acc[mt][nt][1];
            ep[(r0+8) * 132 + col]   = acc[mt][nt][2];
            ep[(r0+8) * 132 + col+1] = acc[mt][nt][3];
        }
    }
    __syncthreads();

    {
        int r = tid >> 1, half = tid & 1;
        ll row = (ll)z * MrowsPerZ + m0 + r;
        int cbase = half * 64;
        const float* bb = bias + (ll)z * biasPerZ + n0 + cbase;
#pragma unroll
        for (int q = 0; q < 8; q++) {
            float v[8];
#pragma unroll
            for (int j = 0; j < 8; j++)
                v[j] = ep[r * 132 + cbase + q * 8 + j] + bb[q * 8 + j];
            if (OUTMODE == 0) {
                float* o = (float*)outp + row * (ll)N + n0 + cbase + q * 8;
                float4 o0 = {v[0], v[1], v[2], v[3]};
                float4 o1 = {v[4], v[5], v[6], v[7]};
                ((float4*)o)[0] = o0; ((float4*)o)[1] = o1;
            } else {
                __align__(16) uint16_t hs[8], ms[8], ls[8];
#pragma unroll
                for (int j = 0; j < 8; j++) {
                    float vv = fmaxf(v[j], 0.f);
                    split3v(vv, hs + j, ms + j, ls + j);
                }
                bf16* o0 = (bf16*)outp + row * (ll)N + n0 + cbase + q * 8;
                *(uint4*)o0 = *(uint4*)hs;
                *(uint4*)(o0 + OpS) = *(uint4*)ms;
                if (OUTMODE == 1) *(uint4*)(o0 + 2 * OpS) = *(uint4*)ls;
            }
        }
    }
}

// ---------------- router logits + softmax + top-2 (reads 3 bf16 planes) ----------------
__global__ __launch_bounds__(128)
void router_topk3_kernel(const bf16* __restrict__ h2s, ll ps,
                         const float* __restrict__ Wr3, const float* __restrict__ br3,
                         float* __restrict__ topk_p, int* __restrict__ topk_e)
{
    int tok = (blockIdx.x * blockDim.x + threadIdx.x) >> 5;
    int lane = threadIdx.x & 31;
    if (tok >= BT) return;
    const bf16* r0 = h2s + (ll)tok * HH;
    const bf16* r1 = r0 + ps;
    const bf16* r2 = r1 + ps;

    float acc[EE];
#pragma unroll
    for (int e = 0; e < EE; e++) acc[e] = 0.f;

    for (int k = lane * 4; k < HH; k += 128) {
        float vv[4];
#pragma unroll
        for (int h = 0; h < 2; h++) {
            __nv_bfloat162 a = *(const __nv_bfloat162*)(r0 + k + 2 * h);
            __nv_bfloat162 b = *(const __nv_bfloat162*)(r1 + k + 2 * h);
            __nv_bfloat162 c = *(const __nv_bfloat162*)(r2 + k + 2 * h);
            vv[2*h+0] = __bfloat162float(a.x) + __bfloat162float(b.x) + __bfloat162float(c.x);
            vv[2*h+1] = __bfloat162float(a.y) + __bfloat162float(b.y) + __bfloat162float(c.y);
        }
#pragma unroll
        for (int j = 0; j < 4; j++) {
            const float* w = Wr3 + (ll)(k + j) * EE;
            float xv = vv[j];
#pragma unroll
            for (int e = 0; e < EE; e++) acc[e] += xv * w[e];
        }
    }
#pragma unroll
    for (int e = 0; e < EE; e++)
#pragma unroll
        for (int off = 16; off > 0; off >>= 1)
            acc[e] += __shfl_xor_sync(0xFFFFFFFFu, acc[e], off);

    if (lane == 0) {
        float lg[EE], mx = -1e30f;
#pragma unroll
        for (int e = 0; e < EE; e++) { lg[e] = acc[e] + br3[e]; mx = fmaxf(mx, lg[e]); }
        float p[EE], s = 0.f;
#pragma unroll
        for (int e = 0; e < EE; e++) { p[e] = __expf(lg[e] - mx); s += p[e]; }
        float inv = 1.f / s;
        int i0 = 0;
#pragma unroll
        for (int e = 1; e < EE; e++) if (lg[e] > lg[i0]) i0 = e;
        int i1 = (i0 == 0) ? 1 : 0;
#pragma unroll
        for (int e = 0; e < EE; e++) if (e != i0 && lg[e] > lg[i1]) i1 = e;
        topk_p[tok * 2 + 0] = p[i0] * inv;
        topk_p[tok * 2 + 1] = p[i1] * inv;
        topk_e[tok * 2 + 0] = i0;
        topk_e[tok * 2 + 1] = i1;
    }
}

__global__ void init_slots_kernel(int* slot_tok) {
    int i = blockIdx.x * 256 + threadIdx.x;
    if (i < NSLOT) slot_tok[i] = -1;
}

__global__ __launch_bounds__(256)
void route_scan_kernel(const int* __restrict__ te, int* __restrict__ dest, int* __restrict__ slot_tok)
{
    __shared__ int se[TT * KTOP];
    int b = blockIdx.x;
    for (int i = threadIdx.x; i < TT * KTOP; i += 256) se[i] = te[b * TT * KTOP + i];
    __syncthreads();
    if (threadIdx.x < EE) {
        int e = threadIdx.x, cnt = 0;
        for (int i = 0; i < TT * KTOP; i++) {
            if (se[i] == e) {
                int gi = b * TT * KTOP + i;
                if (cnt < CAPQ) {
                    int s = e * (BB * CAPQ) + b * CAPQ + cnt;
                    dest[gi] = s;
                    slot_tok[s] = b * TT + (i >> 1);
                } else dest[gi] = -1;
                cnt++;
            }
        }
    }
}

__global__ __launch_bounds__(256)
void combine_kernel(const float* __restrict__ ey, const float* __restrict__ topk_p,
                    const int* __restrict__ dest, float* __restrict__ out)
{
    int tok = blockIdx.x;
    int c = threadIdx.x * 4;
    float4 r = make_float4(0.f, 0.f, 0.f, 0.f);
#pragma unroll
    for (int k = 0; k < KTOP; k++) {
        int s = dest[tok * 2 + k];
        if (s >= 0) {
            float p = topk_p[tok * 2 + k];
            float4 v = *(const float4*)(ey + (ll)s * CC + c);
            r.x += p * v.x; r.y += p * v.y; r.z += p * v.z; r.w += p * v.w;
        }
    }
    *(float4*)(out + (ll)tok * CC + c) = r;
}

// ---------------- launch ----------------
extern "C" void kernel_launch(void* const* d_in, const int* in_sizes, int n_in,
                              void* d_out, int out_size)
{
    (void)in_sizes; (void)n_in; (void)out_size;
    const float* x   = (const float*)d_in[0];
    const float* Wr1 = (const float*)d_in[1];
    const float* br1 = (const float*)d_in[2];
    const float* Wr2 = (const float*)d_in[3];
    const float* br2 = (const float*)d_in[4];
    const float* Wr3 = (const float*)d_in[5];
    const float* br3 = (const float*)d_in[6];
    const float* We1 = (const float*)d_in[7];
    const float* be1 = (const float*)d_in[8];
    const float* We2 = (const float*)d_in[9];
    const float* be2 = (const float*)d_in[10];
    float* out = (float*)d_out;

    bf16 *xs, *wr1t, *wr2t, *we1t, *we2t, *h1s, *h2s, *ehs;
    float *ey, *tp; int *te, *dest, *stok;
    cudaGetSymbolAddress((void**)&xs,   g_xs);
    cudaGetSymbolAddress((void**)&wr1t, g_wr1t);
    cudaGetSymbolAddress((void**)&wr2t, g_wr2t);
    cudaGetSymbolAddress((void**)&we1t, g_we1t);
    cudaGetSymbolAddress((void**)&we2t, g_we2t);
    cudaGetSymbolAddress((void**)&h1s,  g_h1s);
    cudaGetSymbolAddress((void**)&h2s,  g_h2s);
    cudaGetSymbolAddress((void**)&ehs,  g_ehs);
    cudaGetSymbolAddress((void**)&ey,   g_ey);
    cudaGetSymbolAddress((void**)&tp,   g_topk_p);
    cudaGetSymbolAddress((void**)&te,   g_topk_e);
    cudaGetSymbolAddress((void**)&dest, g_dest);
    cudaGetSymbolAddress((void**)&stok, g_slot_tok);

    const int SM3 = 2 * 3 * 2 * 10240;   // 122880
    const int SM2 = 2 * 2 * 2 * 10240;   //  81920
    static int smem_set = 0;
    if (!smem_set) {
        cudaFuncSetAttribute(tc_gemm<3,1>, cudaFuncAttributeMaxDynamicSharedMemorySize, SM3);
        cudaFuncSetAttribute(tc_gemm<2,2>, cudaFuncAttributeMaxDynamicSharedMemorySize, SM2);
        cudaFuncSetAttribute(tc_gemm<2,0>, cudaFuncAttributeMaxDynamicSharedMemorySize, SM2);
        smem_set = 1;
    }

    // 0) input splits / weight transposes
    split3_kernel<<<(ll)BT * CC / 4 / 256, 256>>>(x, xs, (ll)BT * CC);
    transpose_split_kernel<<<dim3(HH/32, CC/32, 1), dim3(32,8)>>>(Wr1, wr1t, CC, HH, (ll)HH*CC, 3);
    transpose_split_kernel<<<dim3(HH/32, HH/32, 1), dim3(32,8)>>>(Wr2, wr2t, (ll)HH, HH, (ll)HH*HH, 3);
    transpose_split_kernel<<<dim3(HH/32, CC/32, EE), dim3(32,8)>>>(We1, we1t, CC, HH, (ll)EE*HH*CC, 2);
    transpose_split_kernel<<<dim3(CC/32, HH/32, EE), dim3(32,8)>>>(We2, we2t, HH, CC, (ll)EE*CC*HH, 2);

    // 1) h1 = relu(x @ Wr1 + br1) : split3 out
    tc_gemm<3,1><<<dim3((BT/128)*(HH/128), 1), 256, SM3>>>(
        xs, (ll)BT*CC, BT, wr1t, (ll)HH*CC, br1, 0,
        h1s, (ll)BT*HH, BT, nullptr, 0, HH, CC, BT/128, HH/128);

    // 2) h2 = relu(h1 @ Wr2 + br2) : split3 out
    tc_gemm<3,1><<<dim3((BT/128)*(HH/128), 1), 256, SM3>>>(
        h1s, (ll)BT*HH, BT, wr2t, (ll)HH*HH, br2, 0,
        h2s, (ll)BT*HH, BT, nullptr, 0, HH, HH, BT/128, HH/128);

    // 3) logits -> softmax -> top-2
    router_topk3_kernel<<<(BT * 32) / 128, 128>>>(h2s, (ll)BT*HH, Wr3, br3, tp, te);

    // 4) routing tables
    init_slots_kernel<<<(NSLOT + 255) / 256, 256>>>(stok);
    route_scan_kernel<<<BB, 256>>>(te, dest, stok);

    // 5) eh[e] = relu(gather(x) @ We1[e] + be1[e]) : split2 out
    tc_gemm<2,2><<<dim3((ROWS_E/128)*(HH/128), EE), 256, SM2>>>(
        xs, (ll)BT*CC, ROWS_E, we1t, (ll)EE*HH*CC, be1, HH,
        ehs, (ll)EE*ROWS_E*HH, ROWS_E, stok, ROWS_E, HH, CC, ROWS_E/128, HH/128);

    // 6) ey[e] = eh[e] @ We2[e] + be2[e] : fp32 out
    tc_gemm<2,0><<<dim3((ROWS_E/128)*(CC/128), EE), 256, SM2>>>(
        ehs, (ll)EE*ROWS_E*HH, ROWS_E, we2t, (ll)EE*CC*HH, be2, CC,
        ey, 0, ROWS_E, nullptr, 0, CC, HH, ROWS_E/128, CC/128);

    // 7) combine
    combine_kernel<<<BT, 256>>>(ey, tp, dest, out);
}

// round 5
// speedup vs baseline: 2.6429x; 1.0640x over previous
#include <cuda_runtime.h>
#include <cuda_bf16.h>
#include <stdint.h>

#define BB   8
#define TT   2048
#define CC   1024
#define EE   8
#define KTOP 2
#define CAPQ 320
#define HH   4096
#define BT   (BB*TT)
#define NSLOT (EE*BB*CAPQ)
#define ROWS_E (BB*CAPQ)

typedef __nv_bfloat16 bf16;
typedef long long ll;

// ---------------- scratch ----------------
__device__ bf16  g_xs  [3ll*BT*CC];        // x planes [p][BT][CC]
__device__ bf16  g_wr1t[3ll*CC*HH];        // Wr1 planes [p][K=CC][N=HH]
__device__ bf16  g_wr2t[3ll*HH*HH];        // Wr2 planes [p][K=HH][N=HH]
__device__ bf16  g_we1t[2ll*EE*CC*HH];     // We1 planes [p][E][K=CC][N=HH]
__device__ bf16  g_we2t[2ll*EE*HH*CC];     // We2 planes [p][E][K=HH][N=CC]
__device__ bf16  g_h1s [3ll*BT*HH];
__device__ bf16  g_h2s [3ll*BT*HH];
__device__ bf16  g_ehs [2ll*EE*ROWS_E*HH];
__device__ float g_ey  [(ll)EE*ROWS_E*CC];
__device__ float g_topk_p[BT*KTOP];
__device__ int   g_topk_e[BT*KTOP];
__device__ int   g_dest[BT*KTOP];
__device__ int   g_slot_tok[NSLOT];

// ---------------- PTX helpers ----------------
__device__ __forceinline__ uint32_t smem_u32(const void* p) {
    uint32_t a;
    asm("{ .reg .u64 t; cvta.to.shared.u64 t, %1; cvt.u32.u64 %0, t; }" : "=r"(a) : "l"(p));
    return a;
}
__device__ __forceinline__ void cp16(uint32_t dst, const void* src, int ssz) {
    asm volatile("cp.async.cg.shared.global [%0], [%1], 16, %2;" :: "r"(dst), "l"(src), "r"(ssz));
}
__device__ __forceinline__ void cp_commit() { asm volatile("cp.async.commit_group;" ::: "memory"); }
template<int N> __device__ __forceinline__ void cp_wait() {
    asm volatile("cp.async.wait_group %0;" :: "n"(N) : "memory");
}
__device__ __forceinline__ void ldsm4(uint32_t* r, uint32_t addr) {
    asm volatile("ldmatrix.sync.aligned.m8n8.x4.shared.b16 {%0,%1,%2,%3}, [%4];"
        : "=r"(r[0]), "=r"(r[1]), "=r"(r[2]), "=r"(r[3]) : "r"(addr));
}
__device__ __forceinline__ void ldsm4t(uint32_t* r, uint32_t addr) {
    asm volatile("ldmatrix.sync.aligned.m8n8.x4.trans.shared.b16 {%0,%1,%2,%3}, [%4];"
        : "=r"(r[0]), "=r"(r[1]), "=r"(r[2]), "=r"(r[3]) : "r"(addr));
}
__device__ __forceinline__ void mma_bf16(float* c, const uint32_t* a, const uint32_t* b) {
    asm volatile("mma.sync.aligned.m16n8k16.row.col.f32.bf16.bf16.f32 "
        "{%0,%1,%2,%3}, {%4,%5,%6,%7}, {%8,%9}, {%0,%1,%2,%3};"
        : "+f"(c[0]), "+f"(c[1]), "+f"(c[2]), "+f"(c[3])
        : "r"(a[0]), "r"(a[1]), "r"(a[2]), "r"(a[3]), "r"(b[0]), "r"(b[1]));
}

// ---------------- splitting helpers ----------------
__device__ __forceinline__ void split3v(float v, uint16_t* h, uint16_t* m, uint16_t* l) {
    bf16 hb = __float2bfloat16(v);
    float r1 = v - __bfloat162float(hb);
    bf16 mb = __float2bfloat16(r1);
    bf16 lb = __float2bfloat16(r1 - __bfloat162float(mb));
    *h = *(uint16_t*)&hb; *m = *(uint16_t*)&mb; *l = *(uint16_t*)&lb;
}

template<int NPL>
__global__ __launch_bounds__(256)
void splitN_kernel(const float* __restrict__ in, bf16* __restrict__ out, ll ps) {
    ll i = ((ll)blockIdx.x * 256 + threadIdx.x) * 4;
    float4 v = *(const float4*)(in + i);
    uint16_t h[4], m[4], l[4];
    split3v(v.x, h+0, m+0, l+0); split3v(v.y, h+1, m+1, l+1);
    split3v(v.z, h+2, m+2, l+2); split3v(v.w, h+3, m+3, l+3);
    *(uint2*)(out + i)      = *(uint2*)h;
    *(uint2*)(out + ps + i) = *(uint2*)m;
    if (NPL == 3) *(uint2*)(out + 2*ps + i) = *(uint2*)l;
}

// ---------------- split-bf16 GEMM via mma.sync (HMMA) ----------------
// C[z] = act( sum_{ia+ib<NP} A_plane[ia] @ B_plane[ib] + bias )
// A [M,K] row-major (optionally row-gathered); B planes [z][K][N] row-major
// (loaded via ldmatrix.trans). Tile 128x128x32, 8 warps (4m x 2n), 3-stage cp.async.
// OUTMODE: 0 = fp32; 1 = relu+split3 planes; 2 = relu+split2 planes.
#define PT_A 10240   // 128 rows x 80B
#define PT_B 8704    // 32 rows x 272B
template<int NP, int OUTMODE>
__global__ __launch_bounds__(256, 1)
void tc_gemm(const bf16* __restrict__ A, ll ApS, int ArowsPerZ,
             const bf16* __restrict__ B, ll BpS,
             const float* __restrict__ bias, int biasPerZ,
             void* __restrict__ outp, ll OpS, int MrowsPerZ,
             const int* __restrict__ gidx, int gstride,
             int N, int K, int gm, int gn)
{
    extern __shared__ char sm[];
    __shared__ int rowtok[128];
    const uint32_t smb = smem_u32(sm);
    const int tid = threadIdx.x;
    const int wid = tid >> 5, lane = tid & 31;
    const int z = blockIdx.y;

    // grouped rasterization for L2 reuse
    int bid = blockIdx.x;
    int grp = bid / (gn * 8);
    int rem = bid - grp * gn * 8;
    int gsz = gm - grp * 8; if (gsz > 8) gsz = 8;
    int mtile = grp * 8 + rem % gsz;
    int ntile = rem / gsz;
    const int m0 = mtile << 7, n0 = ntile << 7;

    if (tid < 128)
        rowtok[tid] = gidx ? gidx[(ll)z * gstride + m0 + tid] : (z * ArowsPerZ + m0 + tid);
    __syncthreads();

    constexpr int stageB = NP * (PT_A + PT_B);
    constexpr int NU = 4 * NP;                 // cp16 units per thread per stage
    const int nch = K >> 5;
    const ll KN = (ll)K * N;

    // hoisted per-thread load descriptors
    const char* srcp[NU];
    uint32_t dsto[NU];
    int ssz[NU];
    ll step[NU];
#pragma unroll
    for (int j = 0; j < NU; j++) {
        int u = tid + j * 256;
        if (u < NP * 512) {                     // A unit
            int p = u >> 9, t = u & 511, r = t >> 2, c = t & 3;
            dsto[j] = (uint32_t)(p * PT_A + r * 80 + c * 16);
            int ra = rowtok[r];
            if (ra < 0) { srcp[j] = (const char*)A; ssz[j] = 0; }
            else { srcp[j] = (const char*)(A + (ll)p * ApS + (ll)ra * K + c * 8); ssz[j] = 16; }
            step[j] = 64;                        // 32 bf16
        } else {                                 // B unit
            int uu = u - NP * 512;
            int p = uu >> 9, t = uu & 511, r = t >> 4, c = t & 15;
            dsto[j] = (uint32_t)(NP * PT_A + p * PT_B + r * 272 + c * 16);
            srcp[j] = (const char*)(B + (ll)p * BpS + (ll)z * KN + (ll)r * N + n0 + c * 8);
            ssz[j] = 16;
            step[j] = (ll)N * 64;                // 32 rows
        }
    }

    auto load_stage = [&](int s) {
        uint32_t sb = smb + s * stageB;
#pragma unroll
        for (int j = 0; j < NU; j++) {
            cp16(sb + dsto[j], srcp[j], ssz[j]);
            srcp[j] += step[j];
        }
        cp_commit();
    };

    const int wm = wid & 3, wn = wid >> 2;
    const uint32_t a_off = (uint32_t)((wm * 32 + (lane & 15)) * 80 + (lane >> 4) * 16);
    const uint32_t b_off = (uint32_t)((lane & 15) * 272 + (lane >> 4) * 16);

    float acc[2][8][4];
#pragma unroll
    for (int mt = 0; mt < 2; mt++)
#pragma unroll
        for (int nt = 0; nt < 8; nt++)
#pragma unroll
            for (int j = 0; j < 4; j++) acc[mt][nt][j] = 0.f;

    load_stage(0);
    load_stage(1);

    int cur = 0;
    for (int i = 0; i < nch; i++) {
        if (i + 1 < nch) cp_wait<1>(); else cp_wait<0>();
        __syncthreads();
        if (i + 2 < nch) load_stage((cur + 2 >= 3) ? cur - 1 : cur + 2);

        uint32_t sbase = smb + cur * stageB;
#pragma unroll
        for (int ks = 0; ks < 2; ks++) {
            uint32_t aF[NP][2][4];
#pragma unroll
            for (int p = 0; p < NP; p++)
#pragma unroll
                for (int mt = 0; mt < 2; mt++)
                    ldsm4(aF[p][mt], sbase + p * PT_A + mt * 16 * 80 + ks * 32 + a_off);
#pragma unroll
            for (int ib = 0; ib < NP; ib++) {
                uint32_t bF[8][2];
#pragma unroll
                for (int q = 0; q < 4; q++) {
                    uint32_t r4[4];
                    ldsm4t(r4, sbase + NP * PT_A + ib * PT_B + ks * 4352
                               + (uint32_t)((wn * 64 + q * 16) * 2) + b_off);
                    bF[q*2][0] = r4[0]; bF[q*2][1] = r4[1];
                    bF[q*2+1][0] = r4[2]; bF[q*2+1][1] = r4[3];
                }
#pragma unroll
                for (int ia = 0; ia < NP; ia++) {
                    if (ia + ib >= NP) continue;
#pragma unroll
                    for (int mt = 0; mt < 2; mt++)
#pragma unroll
                        for (int nt = 0; nt < 8; nt++)
                            mma_bf16(acc[mt][nt], aF[ia][mt], bF[nt]);
                }
            }
        }
        cur = (cur + 1 >= 3) ? 0 : cur + 1;
        if (i + 1 < nch) __syncthreads();   // readers done before next overwrite window
    }

    // ---- epilogue: stage fp32 tile in SMEM, coalesced bias/relu/split stores ----
    __syncthreads();
    float* ep = (float*)sm;
#pragma unroll
    for (int mt = 0; mt < 2; mt++) {
        int r0 = wm * 32 + mt * 16 + (lane >> 2);
#pragma unroll
        for (int nt = 0; nt < 8; nt++) {
            int col = wn * 64 + nt * 8 + (lane & 3) * 2;
            ep[r0 * 132 + col]       = acc[mt][nt][0];
            ep[r0 * 132 + col + 1]   = acc[mt][nt][1];
            ep[(r0+8) * 132 + col]   = acc[mt][nt][2];
            ep[(r0+8) * 132 + col+1] = acc[mt][nt][3];
        }
    }
    __syncthreads();

    {
        int r = tid >> 1, half = tid & 1;
        ll row = (ll)z * MrowsPerZ + m0 + r;
        int cbase = half * 64;
        const float* bb = bias + (ll)z * biasPerZ + n0 + cbase;
#pragma unroll
        for (int q = 0; q < 8; q++) {
            float v[8];
#pragma unroll
            for (int j = 0; j < 8; j++)
                v[j] = ep[r * 132 + cbase + q * 8 + j] + bb[q * 8 + j];
            if (OUTMODE == 0) {
                float* o = (float*)outp + row * (ll)N + n0 + cbase + q * 8;
                float4 o0 = {v[0], v[1], v[2], v[3]};
                float4 o1 = {v[4], v[5], v[6], v[7]};
                ((float4*)o)[0] = o0; ((float4*)o)[1] = o1;
            } else {
                __align__(16) uint16_t hs[8], ms[8], ls[8];
#pragma unroll
                for (int j = 0; j < 8; j++) {
                    float vv = fmaxf(v[j], 0.f);
                    split3v(vv, hs + j, ms + j, ls + j);
                }
                bf16* o0 = (bf16*)outp + row * (ll)N + n0 + cbase + q * 8;
                *(uint4*)o0 = *(uint4*)hs;
                *(uint4*)(o0 + OpS) = *(uint4*)ms;
                if (OUTMODE == 1) *(uint4*)(o0 + 2 * OpS) = *(uint4*)ls;
            }
        }
    }
}

// ---------------- router logits + softmax + top-2 ----------------
__global__ __launch_bounds__(128)
void router_topk3_kernel(const bf16* __restrict__ h2s, ll ps,
                         const float* __restrict__ Wr3, const float* __restrict__ br3,
                         float* __restrict__ topk_p, int* __restrict__ topk_e)
{
    int tok = (blockIdx.x * blockDim.x + threadIdx.x) >> 5;
    int lane = threadIdx.x & 31;
    if (tok >= BT) return;
    const bf16* r0 = h2s + (ll)tok * HH;
    const bf16* r1 = r0 + ps;
    const bf16* r2 = r1 + ps;

    float acc[EE];
#pragma unroll
    for (int e = 0; e < EE; e++) acc[e] = 0.f;

    for (int k = lane * 4; k < HH; k += 128) {
        float vv[4];
#pragma unroll
        for (int h = 0; h < 2; h++) {
            __nv_bfloat162 a = *(const __nv_bfloat162*)(r0 + k + 2 * h);
            __nv_bfloat162 b = *(const __nv_bfloat162*)(r1 + k + 2 * h);
            __nv_bfloat162 c = *(const __nv_bfloat162*)(r2 + k + 2 * h);
            vv[2*h+0] = __bfloat162float(a.x) + __bfloat162float(b.x) + __bfloat162float(c.x);
            vv[2*h+1] = __bfloat162float(a.y) + __bfloat162float(b.y) + __bfloat162float(c.y);
        }
#pragma unroll
        for (int j = 0; j < 4; j++) {
            const float* w = Wr3 + (ll)(k + j) * EE;
            float xv = vv[j];
#pragma unroll
            for (int e = 0; e < EE; e++) acc[e] += xv * w[e];
        }
    }
#pragma unroll
    for (int e = 0; e < EE; e++)
#pragma unroll
        for (int off = 16; off > 0; off >>= 1)
            acc[e] += __shfl_xor_sync(0xFFFFFFFFu, acc[e], off);

    if (lane == 0) {
        float lg[EE], mx = -1e30f;
#pragma unroll
        for (int e = 0; e < EE; e++) { lg[e] = acc[e] + br3[e]; mx = fmaxf(mx, lg[e]); }
        float p[EE], s = 0.f;
#pragma unroll
        for (int e = 0; e < EE; e++) { p[e] = __expf(lg[e] - mx); s += p[e]; }
        float inv = 1.f / s;
        int i0 = 0;
#pragma unroll
        for (int e = 1; e < EE; e++) if (lg[e] > lg[i0]) i0 = e;
        int i1 = (i0 == 0) ? 1 : 0;
#pragma unroll
        for (int e = 0; e < EE; e++) if (e != i0 && lg[e] > lg[i1]) i1 = e;
        topk_p[tok * 2 + 0] = p[i0] * inv;
        topk_p[tok * 2 + 1] = p[i1] * inv;
        topk_e[tok * 2 + 0] = i0;
        topk_e[tok * 2 + 1] = i1;
    }
}

__global__ void init_slots_kernel(int* slot_tok) {
    int i = blockIdx.x * 256 + threadIdx.x;
    if (i < NSLOT) slot_tok[i] = -1;
}

__global__ __launch_bounds__(256)
void route_scan_kernel(const int* __restrict__ te, int* __restrict__ dest, int* __restrict__ slot_tok)
{
    __shared__ int se[TT * KTOP];
    int b = blockIdx.x;
    for (int i = threadIdx.x; i < TT * KTOP; i += 256) se[i] = te[b * TT * KTOP + i];
    __syncthreads();
    if (threadIdx.x < EE) {
        int e = threadIdx.x, cnt = 0;
        for (int i = 0; i < TT * KTOP; i++) {
            if (se[i] == e) {
                int gi = b * TT * KTOP + i;
                if (cnt < CAPQ) {
                    int s = e * (BB * CAPQ) + b * CAPQ + cnt;
                    dest[gi] = s;
                    slot_tok[s] = b * TT + (i >> 1);
                } else dest[gi] = -1;
                cnt++;
            }
        }
    }
}

__global__ __launch_bounds__(256)
void combine_kernel(const float* __restrict__ ey, const float* __restrict__ topk_p,
                    const int* __restrict__ dest, float* __restrict__ out)
{
    int tok = blockIdx.x;
    int c = threadIdx.x * 4;
    float4 r = make_float4(0.f, 0.f, 0.f, 0.f);
#pragma unroll
    for (int k = 0; k < KTOP; k++) {
        int s = dest[tok * 2 + k];
        if (s >= 0) {
            float p = topk_p[tok * 2 + k];
            float4 v = *(const float4*)(ey + (ll)s * CC + c);
            r.x += p * v.x; r.y += p * v.y; r.z += p * v.z; r.w += p * v.w;
        }
    }
    *(float4*)(out + (ll)tok * CC + c) = r;
}

// ---------------- launch ----------------
extern "C" void kernel_launch(void* const* d_in, const int* in_sizes, int n_in,
                              void* d_out, int out_size)
{
    (void)in_sizes; (void)n_in; (void)out_size;
    const float* x   = (const float*)d_in[0];
    const float* Wr1 = (const float*)d_in[1];
    const float* br1 = (const float*)d_in[2];
    const float* Wr2 = (const float*)d_in[3];
    const float* br2 = (const float*)d_in[4];
    const float* Wr3 = (const float*)d_in[5];
    const float* br3 = (const float*)d_in[6];
    const float* We1 = (const float*)d_in[7];
    const float* be1 = (const float*)d_in[8];
    const float* We2 = (const float*)d_in[9];
    const float* be2 = (const float*)d_in[10];
    float* out = (float*)d_out;

    bf16 *xs, *wr1t, *wr2t, *we1t, *we2t, *h1s, *h2s, *ehs;
    float *ey, *tp; int *te, *dest, *stok;
    cudaGetSymbolAddress((void**)&xs,   g_xs);
    cudaGetSymbolAddress((void**)&wr1t, g_wr1t);
    cudaGetSymbolAddress((void**)&wr2t, g_wr2t);
    cudaGetSymbolAddress((void**)&we1t, g_we1t);
    cudaGetSymbolAddress((void**)&we2t, g_we2t);
    cudaGetSymbolAddress((void**)&h1s,  g_h1s);
    cudaGetSymbolAddress((void**)&h2s,  g_h2s);
    cudaGetSymbolAddress((void**)&ehs,  g_ehs);
    cudaGetSymbolAddress((void**)&ey,   g_ey);
    cudaGetSymbolAddress((void**)&tp,   g_topk_p);
    cudaGetSymbolAddress((void**)&te,   g_topk_e);
    cudaGetSymbolAddress((void**)&dest, g_dest);
    cudaGetSymbolAddress((void**)&stok, g_slot_tok);

    const int SM3 = 3 * 3 * (PT_A + PT_B);   // 170496
    const int SM2 = 3 * 2 * (PT_A + PT_B);   // 113664
    static int smem_set = 0;
    if (!smem_set) {
        cudaFuncSetAttribute(tc_gemm<3,1>, cudaFuncAttributeMaxDynamicSharedMemorySize, SM3);
        cudaFuncSetAttribute(tc_gemm<2,2>, cudaFuncAttributeMaxDynamicSharedMemorySize, SM2);
        cudaFuncSetAttribute(tc_gemm<2,0>, cudaFuncAttributeMaxDynamicSharedMemorySize, SM2);
        smem_set = 1;
    }

    // 0) elementwise splits (no transposes: weights stay [K][N])
    splitN_kernel<3><<<(ll)BT * CC / 1024, 256>>>(x,   xs,   (ll)BT * CC);
    splitN_kernel<3><<<(ll)CC * HH / 1024, 256>>>(Wr1, wr1t, (ll)CC * HH);
    splitN_kernel<3><<<(ll)HH * HH / 1024, 256>>>(Wr2, wr2t, (ll)HH * HH);
    splitN_kernel<2><<<(ll)EE * CC * HH / 1024, 256>>>(We1, we1t, (ll)EE * CC * HH);
    splitN_kernel<2><<<(ll)EE * HH * CC / 1024, 256>>>(We2, we2t, (ll)EE * HH * CC);

    // 1) h1 = relu(x @ Wr1 + br1) : split3 out
    tc_gemm<3,1><<<dim3((BT/128)*(HH/128), 1), 256, SM3>>>(
        xs, (ll)BT*CC, BT, wr1t, (ll)CC*HH, br1, 0,
        h1s, (ll)BT*HH, BT, nullptr, 0, HH, CC, BT/128, HH/128);

    // 2) h2 = relu(h1 @ Wr2 + br2) : split3 out
    tc_gemm<3,1><<<dim3((BT/128)*(HH/128), 1), 256, SM3>>>(
        h1s, (ll)BT*HH, BT, wr2t, (ll)HH*HH, br2, 0,
        h2s, (ll)BT*HH, BT, nullptr, 0, HH, HH, BT/128, HH/128);

    // 3) logits -> softmax -> top-2
    router_topk3_kernel<<<(BT * 32) / 128, 128>>>(h2s, (ll)BT*HH, Wr3, br3, tp, te);

    // 4) routing tables
    init_slots_kernel<<<(NSLOT + 255) / 256, 256>>>(stok);
    route_scan_kernel<<<BB, 256>>>(te, dest, stok);

    // 5) eh[e] = relu(gather(x) @ We1[e] + be1[e]) : split2 out
    tc_gemm<2,2><<<dim3((ROWS_E/128)*(HH/128), EE), 256, SM2>>>(
        xs, (ll)BT*CC, ROWS_E, we1t, (ll)EE*CC*HH, be1, HH,
        ehs, (ll)EE*ROWS_E*HH, ROWS_E, stok, ROWS_E, HH, CC, ROWS_E/128, HH/128);

    // 6) ey[e] = eh[e] @ We2[e] + be2[e] : fp32 out
    tc_gemm<2,0><<<dim3((ROWS_E/128)*(CC/128), EE), 256, SM2>>>(
        ehs, (ll)EE*ROWS_E*HH, ROWS_E, we2t, (ll)EE*HH*CC, be2, CC,
        ey, 0, ROWS_E, nullptr, 0, CC, HH, ROWS_E/128, CC/128);

    // 7) combine
    combine_kernel<<<BT, 256>>>(ey, tp, dest, out);
}

// round 9
// speedup vs baseline: 3.5811x; 1.3550x over previous
#include <cuda_runtime.h>
#include <cuda_bf16.h>
#include <stdint.h>

#define BB   8
#define TT   2048
#define CC   1024
#define EE   8
#define KTOP 2
#define CAPQ 320
#define HH   4096
#define BT   (BB*TT)
#define NSLOT (EE*BB*CAPQ)
#define ROWS_E (BB*CAPQ)
#define FIXCAP 512
#define FIX_THRESH 1e-3f

typedef __nv_bfloat16 bf16;
typedef long long ll;

// ---------------- scratch ----------------
__device__ bf16  g_xs  [3ll*BT*CC];        // x planes (3: fixup uses all, main uses 2)
__device__ bf16  g_wr1t[3ll*CC*HH];        // Wr1 planes [p][K][N]
__device__ bf16  g_wr2t[3ll*HH*HH];        // Wr2 planes
__device__ bf16  g_we1t[2ll*EE*CC*HH];
__device__ bf16  g_we2t[2ll*EE*HH*CC];
__device__ bf16  g_h1s [2ll*BT*HH];        // split2 router activations
__device__ bf16  g_h2s [2ll*BT*HH];
__device__ bf16  g_h1f [3ll*FIXCAP*HH];    // fixup split3 activations
__device__ bf16  g_h2f [3ll*FIXCAP*HH];
__device__ bf16  g_ehs [2ll*EE*ROWS_E*HH];
__device__ float g_ey  [(ll)EE*ROWS_E*CC];
__device__ float g_topk_p[BT*KTOP];
__device__ int   g_topk_e[BT*KTOP];
__device__ int   g_dest[BT*KTOP];
__device__ int   g_slot_tok[NSLOT];
__device__ int   g_fix_tok[FIXCAP];
__device__ int   g_fix_cnt;

// ---------------- PTX helpers ----------------
__device__ __forceinline__ uint32_t smem_u32(const void* p) {
    uint32_t a;
    asm("{ .reg .u64 t; cvta.to.shared.u64 t, %1; cvt.u32.u64 %0, t; }" : "=r"(a) : "l"(p));
    return a;
}
__device__ __forceinline__ void cp16(uint32_t dst, const void* src, int ssz) {
    asm volatile("cp.async.cg.shared.global [%0], [%1], 16, %2;" :: "r"(dst), "l"(src), "r"(ssz));
}
__device__ __forceinline__ void cp_commit() { asm volatile("cp.async.commit_group;" ::: "memory"); }
template<int N> __device__ __forceinline__ void cp_wait() {
    asm volatile("cp.async.wait_group %0;" :: "n"(N) : "memory");
}
__device__ __forceinline__ void ldsm4(uint32_t* r, uint32_t addr) {
    asm volatile("ldmatrix.sync.aligned.m8n8.x4.shared.b16 {%0,%1,%2,%3}, [%4];"
        : "=r"(r[0]), "=r"(r[1]), "=r"(r[2]), "=r"(r[3]) : "r"(addr));
}
__device__ __forceinline__ void ldsm4t(uint32_t* r, uint32_t addr) {
    asm volatile("ldmatrix.sync.aligned.m8n8.x4.trans.shared.b16 {%0,%1,%2,%3}, [%4];"
        : "=r"(r[0]), "=r"(r[1]), "=r"(r[2]), "=r"(r[3]) : "r"(addr));
}
__device__ __forceinline__ void mma_bf16(float* c, const uint32_t* a, const uint32_t* b) {
    asm volatile("mma.sync.aligned.m16n8k16.row.col.f32.bf16.bf16.f32 "
        "{%0,%1,%2,%3}, {%4,%5,%6,%7}, {%8,%9}, {%0,%1,%2,%3};"
        : "+f"(c[0]), "+f"(c[1]), "+f"(c[2]), "+f"(c[3])
        : "r"(a[0]), "r"(a[1]), "r"(a[2]), "r"(a[3]), "r"(b[0]), "r"(b[1]));
}

// ---------------- splitting helpers ----------------
__device__ __forceinline__ void split3v(float v, uint16_t* h, uint16_t* m, uint16_t* l) {
    bf16 hb = __float2bfloat16(v);
    float r1 = v - __bfloat162float(hb);
    bf16 mb = __float2bfloat16(r1);
    bf16 lb = __float2bfloat16(r1 - __bfloat162float(mb));
    *h = *(uint16_t*)&hb; *m = *(uint16_t*)&mb; *l = *(uint16_t*)&lb;
}

template<int NPL>
__global__ __launch_bounds__(256)
void splitN_kernel(const float* __restrict__ in, bf16* __restrict__ out, ll ps) {
    ll i = ((ll)blockIdx.x * 256 + threadIdx.x) * 4;
    float4 v = *(const float4*)(in + i);
    uint16_t h[4], m[4], l[4];
    split3v(v.x, h+0, m+0, l+0); split3v(v.y, h+1, m+1, l+1);
    split3v(v.z, h+2, m+2, l+2); split3v(v.w, h+3, m+3, l+3);
    *(uint2*)(out + i)      = *(uint2*)h;
    *(uint2*)(out + ps + i) = *(uint2*)m;
    if (NPL == 3) *(uint2*)(out + 2*ps + i) = *(uint2*)l;
}

// ---------------- split-bf16 GEMM via mma.sync ----------------
#define PT_A 10240   // 128 rows x 80B
#define PT_B 8704    // 32 rows x 272B
template<int NP, int OUTMODE>
__global__ __launch_bounds__(256, 1)
void tc_gemm(const bf16* __restrict__ A, ll ApS, int ArowsPerZ,
             const bf16* __restrict__ B, ll BpS,
             const float* __restrict__ bias, int biasPerZ,
             void* __restrict__ outp, ll OpS, int MrowsPerZ,
             const int* __restrict__ gidx, int gstride,
             int N, int K, int gm, int gn)
{
    extern __shared__ char sm[];
    __shared__ int rowtok[128];
    const uint32_t smb = smem_u32(sm);
    const int tid = threadIdx.x;
    const int wid = tid >> 5, lane = tid & 31;
    const int z = blockIdx.y;

    int bid = blockIdx.x;
    int grp = bid / (gn * 8);
    int rem = bid - grp * gn * 8;
    int gsz = gm - grp * 8; if (gsz > 8) gsz = 8;
    int mtile = grp * 8 + rem % gsz;
    int ntile = rem / gsz;
    const int m0 = mtile << 7, n0 = ntile << 7;

    if (tid < 128)
        rowtok[tid] = gidx ? gidx[(ll)z * gstride + m0 + tid] : (z * ArowsPerZ + m0 + tid);
    __syncthreads();

    constexpr int stageB = NP * (PT_A + PT_B);
    constexpr int NU = 4 * NP;
    const int nch = K >> 5;
    const ll KN = (ll)K * N;

    const char* srcp[NU];
    uint32_t dsto[NU];
    int ssz[NU];
    ll step[NU];
#pragma unroll
    for (int j = 0; j < NU; j++) {
        int u = tid + j * 256;
        if (u < NP * 512) {
            int p = u >> 9, t = u & 511, r = t >> 2, c = t & 3;
            dsto[j] = (uint32_t)(p * PT_A + r * 80 + c * 16);
            int ra = rowtok[r];
            if (ra < 0) { srcp[j] = (const char*)A; ssz[j] = 0; }
            else { srcp[j] = (const char*)(A + (ll)p * ApS + (ll)ra * K + c * 8); ssz[j] = 16; }
            step[j] = 64;
        } else {
            int uu = u - NP * 512;
            int p = uu >> 9, t = uu & 511, r = t >> 4, c = t & 15;
            dsto[j] = (uint32_t)(NP * PT_A + p * PT_B + r * 272 + c * 16);
            srcp[j] = (const char*)(B + (ll)p * BpS + (ll)z * KN + (ll)r * N + n0 + c * 8);
            ssz[j] = 16;
            step[j] = (ll)N * 64;
        }
    }

    auto load_stage = [&](int s) {
        uint32_t sb = smb + s * stageB;
#pragma unroll
        for (int j = 0; j < NU; j++) {
            cp16(sb + dsto[j], srcp[j], ssz[j]);
            srcp[j] += step[j];
        }
        cp_commit();
    };

    const int wm = wid & 3, wn = wid >> 2;
    const uint32_t a_off = (uint32_t)((wm * 32 + (lane & 15)) * 80 + (lane >> 4) * 16);
    const uint32_t b_off = (uint32_t)((lane & 15) * 272 + (lane >> 4) * 16);

    float acc[2][8][4];
#pragma unroll
    for (int mt = 0; mt < 2; mt++)
#pragma unroll
        for (int nt = 0; nt < 8; nt++)
#pragma unroll
            for (int j = 0; j < 4; j++) acc[mt][nt][j] = 0.f;

    load_stage(0);
    load_stage(1);

    int cur = 0;
    for (int i = 0; i < nch; i++) {
        if (i + 1 < nch) cp_wait<1>(); else cp_wait<0>();
        __syncthreads();
        if (i + 2 < nch) load_stage((cur + 2 >= 3) ? cur - 1 : cur + 2);

        uint32_t sbase = smb + cur * stageB;
#pragma unroll
        for (int ks = 0; ks < 2; ks++) {
            uint32_t aF[NP][2][4];
#pragma unroll
            for (int p = 0; p < NP; p++)
#pragma unroll
                for (int mt = 0; mt < 2; mt++)
                    ldsm4(aF[p][mt], sbase + p * PT_A + mt * 16 * 80 + ks * 32 + a_off);
#pragma unroll
            for (int ib = 0; ib < NP; ib++) {
                uint32_t bF[8][2];
#pragma unroll
                for (int q = 0; q < 4; q++) {
                    uint32_t r4[4];
                    ldsm4t(r4, sbase + NP * PT_A + ib * PT_B + ks * 4352
                               + (uint32_t)((wn * 64 + q * 16) * 2) + b_off);
                    bF[q*2][0] = r4[0]; bF[q*2][1] = r4[1];
                    bF[q*2+1][0] = r4[2]; bF[q*2+1][1] = r4[3];
                }
#pragma unroll
                for (int ia = 0; ia < NP; ia++) {
                    if (ia + ib >= NP) continue;
#pragma unroll
                    for (int mt = 0; mt < 2; mt++)
#pragma unroll
                        for (int nt = 0; nt < 8; nt++)
                            mma_bf16(acc[mt][nt], aF[ia][mt], bF[nt]);
                }
            }
        }
        cur = (cur + 1 >= 3) ? 0 : cur + 1;
        if (i + 1 < nch) __syncthreads();
    }

    __syncthreads();
    float* ep = (float*)sm;
#pragma unroll
    for (int mt = 0; mt < 2; mt++) {
        int r0 = wm * 32 + mt * 16 + (lane >> 2);
#pragma unroll
        for (int nt = 0; nt < 8; nt++) {
            int col = wn * 64 + nt * 8 + (lane & 3) * 2;
            ep[r0 * 132 + col]       = acc[mt][nt][0];
            ep[r0 * 132 + col + 1]   = acc[mt][nt][1];
            ep[(r0+8) * 132 + col]   = acc[mt][nt][2];
            ep[(r0+8) * 132 + col+1] = acc[mt][nt][3];
        }
    }
    __syncthreads();

    {
        int r = tid >> 1, half = tid & 1;
        ll row = (ll)z * MrowsPerZ + m0 + r;
        int cbase = half * 64;
        const float* bb = bias + (ll)z * biasPerZ + n0 + cbase;
#pragma unroll
        for (int q = 0; q < 8; q++) {
            float v[8];
#pragma unroll
            for (int j = 0; j < 8; j++)
                v[j] = ep[r * 132 + cbase + q * 8 + j] + bb[q * 8 + j];
            if (OUTMODE == 0) {
                float* o = (float*)outp + row * (ll)N + n0 + cbase + q * 8;
                float4 o0 = {v[0], v[1], v[2], v[3]};
                float4 o1 = {v[4], v[5], v[6], v[7]};
                ((float4*)o)[0] = o0; ((float4*)o)[1] = o1;
            } else {
                __align__(16) uint16_t hs[8], ms[8], ls[8];
#pragma unroll
                for (int j = 0; j < 8; j++) {
                    float vv = fmaxf(v[j], 0.f);
                    split3v(vv, hs + j, ms + j, ls + j);
                }
                bf16* o0 = (bf16*)outp + row * (ll)N + n0 + cbase + q * 8;
                *(uint4*)o0 = *(uint4*)hs;
                *(uint4*)(o0 + OpS) = *(uint4*)ms;
                if (OUTMODE == 1) *(uint4*)(o0 + 2 * OpS) = *(uint4*)ls;
            }
        }
    }
}

// ---------------- router: logits from NPL planes, softmax, top-2 ----------------
template<int NPL>
__device__ __forceinline__ void router_logits_warp(const bf16* r0, ll ps, const float* Wr3,
                                                   int lane, float* acc)
{
#pragma unroll
    for (int e = 0; e < EE; e++) acc[e] = 0.f;
    for (int k = lane * 4; k < HH; k += 128) {
        float vv[4];
#pragma unroll
        for (int h = 0; h < 2; h++) {
            __nv_bfloat162 a = *(const __nv_bfloat162*)(r0 + k + 2 * h);
            __nv_bfloat162 b = *(const __nv_bfloat162*)(r0 + ps + k + 2 * h);
            float sx = __bfloat162float(a.x) + __bfloat162float(b.x);
            float sy = __bfloat162float(a.y) + __bfloat162float(b.y);
            if (NPL == 3) {
                __nv_bfloat162 c = *(const __nv_bfloat162*)(r0 + 2 * ps + k + 2 * h);
                sx += __bfloat162float(c.x); sy += __bfloat162float(c.y);
            }
            vv[2*h+0] = sx; vv[2*h+1] = sy;
        }
#pragma unroll
        for (int j = 0; j < 4; j++) {
            const float* w = Wr3 + (ll)(k + j) * EE;
            float xv = vv[j];
#pragma unroll
            for (int e = 0; e < EE; e++) acc[e] += xv * w[e];
        }
    }
#pragma unroll
    for (int e = 0; e < EE; e++)
#pragma unroll
        for (int off = 16; off > 0; off >>= 1)
            acc[e] += __shfl_xor_sync(0xFFFFFFFFu, acc[e], off);
}

__device__ __forceinline__ void topk_write(const float* accv, const float* br3,
                                           float* tp, int* te, int tok,
                                           int* fix_tok, int* fix_cnt)
{
    float lg[EE], mx = -1e30f;
#pragma unroll
    for (int e = 0; e < EE; e++) { lg[e] = accv[e] + br3[e]; mx = fmaxf(mx, lg[e]); }
    float p[EE], s = 0.f;
#pragma unroll
    for (int e = 0; e < EE; e++) { p[e] = __expf(lg[e] - mx); s += p[e]; }
    float inv = 1.f / s;
    int i0 = 0;
#pragma unroll
    for (int e = 1; e < EE; e++) if (lg[e] > lg[i0]) i0 = e;
    int i1 = (i0 == 0) ? 1 : 0;
#pragma unroll
    for (int e = 0; e < EE; e++) if (e != i0 && lg[e] > lg[i1]) i1 = e;
    if (fix_tok) {
        float l3 = -1e30f;
#pragma unroll
        for (int e = 0; e < EE; e++) if (e != i0 && e != i1) l3 = fmaxf(l3, lg[e]);
        if (lg[i1] - l3 < FIX_THRESH) {
            int ix = atomicAdd(fix_cnt, 1);
            if (ix < FIXCAP) fix_tok[ix] = tok;
        }
    }
    tp[tok * 2 + 0] = p[i0] * inv;
    tp[tok * 2 + 1] = p[i1] * inv;
    te[tok * 2 + 0] = i0;
    te[tok * 2 + 1] = i1;
}

__global__ __launch_bounds__(128)
void router_topk2_kernel(const bf16* __restrict__ h2s, ll ps,
                         const float* __restrict__ Wr3, const float* __restrict__ br3,
                         float* __restrict__ tp, int* __restrict__ te,
                         int* __restrict__ fix_tok, int* __restrict__ fix_cnt)
{
    int tok = (blockIdx.x * blockDim.x + threadIdx.x) >> 5;
    int lane = threadIdx.x & 31;
    if (tok >= BT) return;
    float acc[EE];
    router_logits_warp<2>(h2s + (ll)tok * HH, ps, Wr3, lane, acc);
    if (lane == 0) topk_write(acc, br3, tp, te, tok, fix_tok, fix_cnt);
}

__global__ __launch_bounds__(128)
void router_fix_kernel(const bf16* __restrict__ h2f, ll ps,
                       const float* __restrict__ Wr3, const float* __restrict__ br3,
                       const int* __restrict__ fix_tok,
                       float* __restrict__ tp, int* __restrict__ te)
{
    int r = (blockIdx.x * blockDim.x + threadIdx.x) >> 5;
    int lane = threadIdx.x & 31;
    if (r >= FIXCAP) return;
    int tok = fix_tok[r];
    if (tok < 0) return;
    float acc[EE];
    router_logits_warp<3>(h2f + (ll)r * HH, ps, Wr3, lane, acc);
    if (lane == 0) topk_write(acc, br3, tp, te, tok, nullptr, nullptr);
}

__global__ void init_fix_kernel(int* fix_tok, int* fix_cnt, int* slot_tok) {
    int i = blockIdx.x * 256 + threadIdx.x;
    if (i < FIXCAP) fix_tok[i] = -1;
    if (i == 0) *fix_cnt = 0;
    if (i < NSLOT) slot_tok[i] = -1;
}

__global__ __launch_bounds__(256)
void route_scan_kernel(const int* __restrict__ te, int* __restrict__ dest, int* __restrict__ slot_tok)
{
    __shared__ int se[TT * KTOP];
    int b = blockIdx.x;
    for (int i = threadIdx.x; i < TT * KTOP; i += 256) se[i] = te[b * TT * KTOP + i];
    __syncthreads();
    if (threadIdx.x < EE) {
        int e = threadIdx.x, cnt = 0;
        for (int i = 0; i < TT * KTOP; i++) {
            if (se[i] == e) {
                int gi = b * TT * KTOP + i;
                if (cnt < CAPQ) {
                    int s = e * (BB * CAPQ) + b * CAPQ + cnt;
                    dest[gi] = s;
                    slot_tok[s] = b * TT + (i >> 1);
                } else dest[gi] = -1;
                cnt++;
            }
        }
    }
}

__global__ __launch_bounds__(256)
void combine_kernel(const float* __restrict__ ey, const float* __restrict__ topk_p,
                    const int* __restrict__ dest, float* __restrict__ out)
{
    int tok = blockIdx.x;
    int c = threadIdx.x * 4;
    float4 r = make_float4(0.f, 0.f, 0.f, 0.f);
#pragma unroll
    for (int k = 0; k < KTOP; k++) {
        int s = dest[tok * 2 + k];
        if (s >= 0) {
            float p = topk_p[tok * 2 + k];
            float4 v = *(const float4*)(ey + (ll)s * CC + c);
            r.x += p * v.x; r.y += p * v.y; r.z += p * v.z; r.w += p * v.w;
        }
    }
    *(float4*)(out + (ll)tok * CC + c) = r;
}

// ---------------- launch ----------------
extern "C" void kernel_launch(void* const* d_in, const int* in_sizes, int n_in,
                              void* d_out, int out_size)
{
    (void)in_sizes; (void)n_in; (void)out_size;
    const float* x   = (const float*)d_in[0];
    const float* Wr1 = (const float*)d_in[1];
    const float* br1 = (const float*)d_in[2];
    const float* Wr2 = (const float*)d_in[3];
    const float* br2 = (const float*)d_in[4];
    const float* Wr3 = (const float*)d_in[5];
    const float* br3 = (const float*)d_in[6];
    const float* We1 = (const float*)d_in[7];
    const float* be1 = (const float*)d_in[8];
    const float* We2 = (const float*)d_in[9];
    const float* be2 = (const float*)d_in[10];
    float* out = (float*)d_out;

    bf16 *xs, *wr1t, *wr2t, *we1t, *we2t, *h1s, *h2s, *h1f, *h2f, *ehs;
    float *ey, *tp; int *te, *dest, *stok, *ftok, *fcnt;
    cudaGetSymbolAddress((void**)&xs,   g_xs);
    cudaGetSymbolAddress((void**)&wr1t, g_wr1t);
    cudaGetSymbolAddress((void**)&wr2t, g_wr2t);
    cudaGetSymbolAddress((void**)&we1t, g_we1t);
    cudaGetSymbolAddress((void**)&we2t, g_we2t);
    cudaGetSymbolAddress((void**)&h1s,  g_h1s);
    cudaGetSymbolAddress((void**)&h2s,  g_h2s);
    cudaGetSymbolAddress((void**)&h1f,  g_h1f);
    cudaGetSymbolAddress((void**)&h2f,  g_h2f);
    cudaGetSymbolAddress((void**)&ehs,  g_ehs);
    cudaGetSymbolAddress((void**)&ey,   g_ey);
    cudaGetSymbolAddress((void**)&tp,   g_topk_p);
    cudaGetSymbolAddress((void**)&te,   g_topk_e);
    cudaGetSymbolAddress((void**)&dest, g_dest);
    cudaGetSymbolAddress((void**)&stok, g_slot_tok);
    cudaGetSymbolAddress((void**)&ftok, g_fix_tok);
    cudaGetSymbolAddress((void**)&fcnt, g_fix_cnt);

    const int SM3 = 3 * 3 * (PT_A + PT_B);   // 170496
    const int SM2 = 3 * 2 * (PT_A + PT_B);   // 113664
    static int smem_set = 0;
    if (!smem_set) {
        cudaFuncSetAttribute(tc_gemm<3,1>, cudaFuncAttributeMaxDynamicSharedMemorySize, SM3);
        cudaFuncSetAttribute(tc_gemm<2,2>, cudaFuncAttributeMaxDynamicSharedMemorySize, SM2);
        cudaFuncSetAttribute(tc_gemm<2,0>, cudaFuncAttributeMaxDynamicSharedMemorySize, SM2);
        smem_set = 1;
    }

    // 0) elementwise splits + table init
    splitN_kernel<3><<<(ll)BT * CC / 1024, 256>>>(x,   xs,   (ll)BT * CC);
    splitN_kernel<3><<<(ll)CC * HH / 1024, 256>>>(Wr1, wr1t, (ll)CC * HH);
    splitN_kernel<3><<<(ll)HH * HH / 1024, 256>>>(Wr2, wr2t, (ll)HH * HH);
    splitN_kernel<2><<<(ll)EE * CC * HH / 1024, 256>>>(We1, we1t, (ll)EE * CC * HH);
    splitN_kernel<2><<<(ll)EE * HH * CC / 1024, 256>>>(We2, we2t, (ll)EE * HH * CC);
    init_fix_kernel<<<(NSLOT + 255) / 256, 256>>>(ftok, fcnt, stok);

    // 1) h1 = relu(x @ Wr1 + br1) : split2 out, split2 math
    tc_gemm<2,2><<<dim3((BT/128)*(HH/128), 1), 256, SM2>>>(
        xs, (ll)BT*CC, BT, wr1t, (ll)CC*HH, br1, 0,
        h1s, (ll)BT*HH, BT, nullptr, 0, HH, CC, BT/128, HH/128);

    // 2) h2 = relu(h1 @ Wr2 + br2) : split2 out, split2 math
    tc_gemm<2,2><<<dim3((BT/128)*(HH/128), 1), 256, SM2>>>(
        h1s, (ll)BT*HH, BT, wr2t, (ll)HH*HH, br2, 0,
        h2s, (ll)BT*HH, BT, nullptr, 0, HH, HH, BT/128, HH/128);

    // 3) logits -> softmax -> top-2, flag marginal tokens (gap23 < FIX_THRESH)
    router_topk2_kernel<<<(BT * 32) / 128, 128>>>(h2s, (ll)BT*HH, Wr3, br3, tp, te, ftok, fcnt);

    // 3b) exact (split3) fixup chain for flagged tokens
    tc_gemm<3,1><<<dim3((FIXCAP/128)*(HH/128), 1), 256, SM3>>>(
        xs, (ll)BT*CC, FIXCAP, wr1t, (ll)CC*HH, br1, 0,
        h1f, (ll)FIXCAP*HH, FIXCAP, ftok, FIXCAP, HH, CC, FIXCAP/128, HH/128);
    tc_gemm<3,1><<<dim3((FIXCAP/128)*(HH/128), 1), 256, SM3>>>(
        h1f, (ll)FIXCAP*HH, FIXCAP, wr2t, (ll)HH*HH, br2, 0,
        h2f, (ll)FIXCAP*HH, FIXCAP, nullptr, 0, HH, HH, FIXCAP/128, HH/128);
    router_fix_kernel<<<(FIXCAP * 32) / 128, 128>>>(h2f, (ll)FIXCAP*HH, Wr3, br3, ftok, tp, te);

    // 4) routing tables
    route_scan_kernel<<<BB, 256>>>(te, dest, stok);

    // 5) eh[e] = relu(gather(x) @ We1[e] + be1[e]) : split2 out
    tc_gemm<2,2><<<dim3((ROWS_E/128)*(HH/128), EE), 256, SM2>>>(
        xs, (ll)BT*CC, ROWS_E, we1t, (ll)EE*CC*HH, be1, HH,
        ehs, (ll)EE*ROWS_E*HH, ROWS_E, stok, ROWS_E, HH, CC, ROWS_E/128, HH/128);

    // 6) ey[e] = eh[e] @ We2[e] + be2[e] : fp32 out
    tc_gemm<2,0><<<dim3((ROWS_E/128)*(CC/128), EE), 256, SM2>>>(
        ehs, (ll)EE*ROWS_E*HH, ROWS_E, we2t, (ll)EE*HH*CC, be2, CC,
        ey, 0, ROWS_E, nullptr, 0, CC, HH, ROWS_E/128, CC/128);

    // 7) combine
    combine_kernel<<<BT, 256>>>(ey, tp, dest, out);
}